// round 1
// baseline (speedup 1.0000x reference)
#include <cuda_runtime.h>
#include <cstdint>

// ---------------- Problem constants ----------------
// B=4, U=64, V=256, IN=STATE=768, CODE=384, HEADS=8, HD=64, INNER=512
#define R_ROWS 256          // B*U
#define S_ROWS 1024         // B*V
#define DIM    768
#define CODE   384
#define INNER  512
#define HEADS  8
#define HD     64
#define BATCH  4
#define U_     64
#define V_     256

// ---------------- Scratch (device globals; no allocs) ----------------
__device__ float g_r  [R_ROWS * DIM];       // LN(receiver) -> then rq = r*(1+mq) lives in g_mq
__device__ float g_s  [S_ROWS * DIM];       // LN(sender)
__device__ float g_mq [R_ROWS * DIM];       // codes@Wmq, then overwritten with rq
__device__ float g_mk [R_ROWS * DIM];
__device__ float g_mv [R_ROWS * DIM];
__device__ float g_me [R_ROWS * INNER];
__device__ float g_q  [R_ROWS * INNER];
__device__ float g_Ak [BATCH * HEADS * U_ * DIM];   // [b][h*64+u][i]
__device__ float g_qbk[R_ROWS * HEADS];
__device__ float g_w  [BATCH * HEADS * U_ * V_];    // scores -> softmax weights
__device__ float g_T  [BATCH * HEADS * U_ * DIM];   // weighted sum of s
__device__ float g_Tm [HEADS * R_ROWS * DIM];       // per-head remap: T * (1+mv)
__device__ float g_msg[R_ROWS * INNER];

// ---------------- LayerNorm (row of 768, 256 threads/row) ----------------
__global__ void ln_kernel(const float* __restrict__ x, const float* __restrict__ g,
                          const float* __restrict__ bb, float* __restrict__ out) {
    int row = blockIdx.x;
    const float* xr = x + (long)row * DIM;
    int t = threadIdx.x;
    float v0 = xr[t], v1 = xr[t + 256], v2 = xr[t + 512];
    float s = v0 + v1 + v2;
    float q = v0 * v0 + v1 * v1 + v2 * v2;
    __shared__ float sh1[8], sh2[8];
    #pragma unroll
    for (int o = 16; o > 0; o >>= 1) {
        s += __shfl_xor_sync(0xffffffffu, s, o);
        q += __shfl_xor_sync(0xffffffffu, q, o);
    }
    if ((t & 31) == 0) { sh1[t >> 5] = s; sh2[t >> 5] = q; }
    __syncthreads();
    if (t == 0) {
        float a = 0.f, c = 0.f;
        #pragma unroll
        for (int i = 0; i < 8; i++) { a += sh1[i]; c += sh2[i]; }
        sh1[0] = a; sh2[0] = c;
    }
    __syncthreads();
    float mu  = sh1[0] * (1.f / 768.f);
    float var = sh2[0] * (1.f / 768.f) - mu * mu;
    float inv = rsqrtf(var + 1e-5f);
    float* o = out + (long)row * DIM;
    o[t]       = (v0 - mu) * inv * g[t]       + bb[t];
    o[t + 256] = (v1 - mu) * inv * g[t + 256] + bb[t + 256];
    o[t + 512] = (v2 - mu) * inv * g[t + 512] + bb[t + 512];
}

// ---------------- Epilogue functors ----------------
struct EpiPlain {
    float* C; int ldc; long cB; const float* bias; long biasB;
    __device__ __forceinline__ void operator()(int z, int m, int n, float acc) const {
        float r = acc;
        if (bias) r += bias[z * biasB + n];
        C[z * cB + (long)m * ldc + n] = r;
    }
};
struct EpiQK {   // acc = (Wk_h^T q_h); multiply mk, scatter into Ak[b][h*64+u][i]
    const float* mk; float* Ak;
    __device__ __forceinline__ void operator()(int h, int m, int n, float acc) const {
        float v = acc * (1.f + mk[(long)m * DIM + n]);
        int b = m >> 6, u = m & 63;
        Ak[(long)b * (HEADS * U_ * DIM) + (long)(h * U_ + u) * DIM + n] = v;
    }
};
struct EpiScores {  // add per-row qbk, scale by 1/8
    const float* qbk; float* w;
    __device__ __forceinline__ void operator()(int b, int m, int n, float acc) const {
        int h = m >> 6, u = m & 63;
        w[(long)b * (HEADS * U_ * V_) + (long)m * V_ + n] =
            (acc + qbk[(b * U_ + u) * HEADS + h]) * 0.125f;
    }
};
struct EpiOut {  // final: recv + (acc+be)*gamma
    const float* recv; const float* be; const float* gamma; float* out;
    __device__ __forceinline__ void operator()(int z, int m, int n, float acc) const {
        (void)z;
        out[(long)m * DIM + n] = recv[(long)m * DIM + n] + (acc + be[n]) * gamma[n];
    }
};

// ---------------- 64x64 tiled GEMM, 4x4 per thread, fp32 ----------------
// C[m,n] = sum_k A[m,k]*B[k,n]   (NN).  Dims: M%64==0, N%64==0, K%16==0.
template <class Epi>
__global__ void gemm64_nn(const float* __restrict__ A, int lda, long aB,
                          const float* __restrict__ B, int ldb, long bB,
                          int K, Epi epi) {
    __shared__ float As[16][68];
    __shared__ float Bs[16][64];
    int z = blockIdx.z;
    const float* Ab = A + (long)z * aB;
    const float* Bb = B + (long)z * bB;
    int m0 = blockIdx.y * 64, n0 = blockIdx.x * 64;
    int tid = threadIdx.x;
    int tx = tid & 15, ty = tid >> 4;
    float acc[4][4] = {};
    for (int k0 = 0; k0 < K; k0 += 16) {
        int c = tid & 15, r = tid >> 4;
        #pragma unroll
        for (int it = 0; it < 4; it++)
            As[c][r + it * 16] = Ab[(long)(m0 + r + it * 16) * lda + k0 + c];
        int j = tid & 63, cr = tid >> 6;
        #pragma unroll
        for (int it = 0; it < 4; it++)
            Bs[cr + it * 4][j] = Bb[(long)(k0 + cr + it * 4) * ldb + n0 + j];
        __syncthreads();
        #pragma unroll
        for (int kk = 0; kk < 16; kk++) {
            float4 a4 = *reinterpret_cast<const float4*>(&As[kk][ty * 4]);
            float4 b4 = *reinterpret_cast<const float4*>(&Bs[kk][tx * 4]);
            float av[4] = {a4.x, a4.y, a4.z, a4.w};
            float bv[4] = {b4.x, b4.y, b4.z, b4.w};
            #pragma unroll
            for (int i = 0; i < 4; i++)
                #pragma unroll
                for (int jj = 0; jj < 4; jj++)
                    acc[i][jj] += av[i] * bv[jj];
        }
        __syncthreads();
    }
    #pragma unroll
    for (int i = 0; i < 4; i++)
        #pragma unroll
        for (int jj = 0; jj < 4; jj++)
            epi(z, m0 + ty * 4 + i, n0 + tx * 4 + jj, acc[i][jj]);
}

// C[m,n] = sum_k A[m,k]*B[n,k]   (NT).
template <class Epi>
__global__ void gemm64_nt(const float* __restrict__ A, int lda, long aB,
                          const float* __restrict__ B, int ldb, long bB,
                          int K, Epi epi) {
    __shared__ float As[16][68];
    __shared__ float Bs[16][68];
    int z = blockIdx.z;
    const float* Ab = A + (long)z * aB;
    const float* Bb = B + (long)z * bB;
    int m0 = blockIdx.y * 64, n0 = blockIdx.x * 64;
    int tid = threadIdx.x;
    int tx = tid & 15, ty = tid >> 4;
    float acc[4][4] = {};
    for (int k0 = 0; k0 < K; k0 += 16) {
        int c = tid & 15, r = tid >> 4;
        #pragma unroll
        for (int it = 0; it < 4; it++)
            As[c][r + it * 16] = Ab[(long)(m0 + r + it * 16) * lda + k0 + c];
        #pragma unroll
        for (int it = 0; it < 4; it++)
            Bs[c][r + it * 16] = Bb[(long)(n0 + r + it * 16) * ldb + k0 + c];
        __syncthreads();
        #pragma unroll
        for (int kk = 0; kk < 16; kk++) {
            float4 a4 = *reinterpret_cast<const float4*>(&As[kk][ty * 4]);
            float4 b4 = *reinterpret_cast<const float4*>(&Bs[kk][tx * 4]);
            float av[4] = {a4.x, a4.y, a4.z, a4.w};
            float bv[4] = {b4.x, b4.y, b4.z, b4.w};
            #pragma unroll
            for (int i = 0; i < 4; i++)
                #pragma unroll
                for (int jj = 0; jj < 4; jj++)
                    acc[i][jj] += av[i] * bv[jj];
        }
        __syncthreads();
    }
    #pragma unroll
    for (int i = 0; i < 4; i++)
        #pragma unroll
        for (int jj = 0; jj < 4; jj++)
            epi(z, m0 + ty * 4 + i, n0 + tx * 4 + jj, acc[i][jj]);
}

// ---------------- Small elementwise / reduction kernels ----------------
__global__ void rq_kernel(const float* __restrict__ r, float* __restrict__ mq) {
    long i = (long)blockIdx.x * 256 + threadIdx.x;   // R_ROWS*DIM
    mq[i] = r[i] * (1.f + mq[i]);
}

__global__ void qbk_kernel(const float* __restrict__ q, const float* __restrict__ bk,
                           float* __restrict__ out) {
    int w = ((int)blockIdx.x * blockDim.x + threadIdx.x) >> 5;  // 2048 warps
    int lane = threadIdx.x & 31;
    int bu = w >> 3, h = w & 7;
    const float* qp = q + (long)bu * INNER + h * HD;
    const float* bp = bk + h * HD;
    float s = qp[lane] * bp[lane] + qp[lane + 32] * bp[lane + 32];
    #pragma unroll
    for (int o = 16; o > 0; o >>= 1) s += __shfl_down_sync(0xffffffffu, s, o);
    if (lane == 0) out[bu * HEADS + h] = s;
}

__global__ void softmax256(float* __restrict__ w) {
    long row = blockIdx.x;
    float* p = w + row * V_;
    int t = threadIdx.x;
    float v = p[t];
    __shared__ float sh[8];
    float m = v;
    #pragma unroll
    for (int o = 16; o > 0; o >>= 1) m = fmaxf(m, __shfl_xor_sync(0xffffffffu, m, o));
    if ((t & 31) == 0) sh[t >> 5] = m;
    __syncthreads();
    if (t == 0) {
        float mm = sh[0];
        #pragma unroll
        for (int i = 1; i < 8; i++) mm = fmaxf(mm, sh[i]);
        sh[0] = mm;
    }
    __syncthreads();
    m = sh[0];
    __syncthreads();
    float e = expf(v - m);
    float s = e;
    #pragma unroll
    for (int o = 16; o > 0; o >>= 1) s += __shfl_xor_sync(0xffffffffu, s, o);
    if ((t & 31) == 0) sh[t >> 5] = s;
    __syncthreads();
    if (t == 0) {
        float ss = 0.f;
        #pragma unroll
        for (int i = 0; i < 8; i++) ss += sh[i];
        sh[0] = ss;
    }
    __syncthreads();
    p[t] = e / sh[0];
}

__global__ void tmv_kernel(const float* __restrict__ T, const float* __restrict__ mv,
                           float* __restrict__ Tm) {
    long t = (long)blockIdx.x * 256 + threadIdx.x;   // HEADS*R_ROWS*DIM
    int i = (int)(t % DIM);
    long rem = t / DIM;
    int m = (int)(rem % R_ROWS);
    int h = (int)(rem / R_ROWS);
    int b = m >> 6, u = m & 63;
    Tm[t] = T[((long)b * (HEADS * U_) + h * U_ + u) * DIM + i] *
            (1.f + mv[(long)m * DIM + i]);
}

__global__ void msgmod_kernel(float* __restrict__ msg, const float* __restrict__ me) {
    long i = (long)blockIdx.x * 256 + threadIdx.x;   // R_ROWS*INNER
    msg[i] *= (1.f + me[i]);
}

// ---------------- Host launcher ----------------
extern "C" void kernel_launch(void* const* d_in, const int* in_sizes, int n_in,
                              void* d_out, int out_size) {
    (void)in_sizes; (void)n_in; (void)out_size;
    const float* recv   = (const float*)d_in[0];
    const float* codes  = (const float*)d_in[1];
    const float* send   = (const float*)d_in[2];
    const float* ln_r_g = (const float*)d_in[3];
    const float* ln_r_b = (const float*)d_in[4];
    const float* ln_s_g = (const float*)d_in[5];
    const float* ln_s_b = (const float*)d_in[6];
    const float* Wq  = (const float*)d_in[7];
    const float* bq  = (const float*)d_in[8];
    const float* Wmq = (const float*)d_in[9];
    const float* Wk  = (const float*)d_in[10];
    const float* bk  = (const float*)d_in[11];
    const float* Wmk = (const float*)d_in[12];
    const float* Wv  = (const float*)d_in[13];
    const float* bv  = (const float*)d_in[14];
    const float* Wmv = (const float*)d_in[15];
    const float* We  = (const float*)d_in[16];
    const float* be  = (const float*)d_in[17];
    const float* Wme = (const float*)d_in[18];
    const float* gamma = (const float*)d_in[19];
    float* out = (float*)d_out;

    float *p_r, *p_s, *p_mq, *p_mk, *p_mv, *p_me, *p_q, *p_Ak, *p_qbk, *p_w, *p_T, *p_Tm, *p_msg;
    cudaGetSymbolAddress((void**)&p_r,   g_r);
    cudaGetSymbolAddress((void**)&p_s,   g_s);
    cudaGetSymbolAddress((void**)&p_mq,  g_mq);
    cudaGetSymbolAddress((void**)&p_mk,  g_mk);
    cudaGetSymbolAddress((void**)&p_mv,  g_mv);
    cudaGetSymbolAddress((void**)&p_me,  g_me);
    cudaGetSymbolAddress((void**)&p_q,   g_q);
    cudaGetSymbolAddress((void**)&p_Ak,  g_Ak);
    cudaGetSymbolAddress((void**)&p_qbk, g_qbk);
    cudaGetSymbolAddress((void**)&p_w,   g_w);
    cudaGetSymbolAddress((void**)&p_T,   g_T);
    cudaGetSymbolAddress((void**)&p_Tm,  g_Tm);
    cudaGetSymbolAddress((void**)&p_msg, g_msg);

    const int TB = 256;

    // 1-2. LayerNorms
    ln_kernel<<<R_ROWS, TB>>>(recv, ln_r_g, ln_r_b, p_r);
    ln_kernel<<<S_ROWS, TB>>>(send, ln_s_g, ln_s_b, p_s);

    // 3-6. Code modulations: codes[256,384] @ Wm*
    {
        EpiPlain e1{p_mq, DIM, 0, nullptr, 0};
        gemm64_nn<<<dim3(DIM / 64, R_ROWS / 64, 1), TB>>>(codes, CODE, 0, Wmq, DIM, 0, CODE, e1);
        EpiPlain e2{p_mk, DIM, 0, nullptr, 0};
        gemm64_nn<<<dim3(DIM / 64, R_ROWS / 64, 1), TB>>>(codes, CODE, 0, Wmk, DIM, 0, CODE, e2);
        EpiPlain e3{p_mv, DIM, 0, nullptr, 0};
        gemm64_nn<<<dim3(DIM / 64, R_ROWS / 64, 1), TB>>>(codes, CODE, 0, Wmv, DIM, 0, CODE, e3);
        EpiPlain e4{p_me, INNER, 0, nullptr, 0};
        gemm64_nn<<<dim3(INNER / 64, R_ROWS / 64, 1), TB>>>(codes, CODE, 0, Wme, INNER, 0, CODE, e4);
    }

    // 7. rq = r * (1+mq)  (overwrites g_mq)
    rq_kernel<<<(R_ROWS * DIM) / TB, TB>>>(p_r, p_mq);

    // 8. q = rq @ Wq + bq   [256,768]x[768,512]
    {
        EpiPlain e{p_q, INNER, 0, bq, 0};
        gemm64_nn<<<dim3(INNER / 64, R_ROWS / 64, 1), TB>>>(p_mq, DIM, 0, Wq, INNER, 0, DIM, e);
    }

    // 9. Ak[b][h*64+u][i] = (1+mk)*(Wk_h^T q_h):  per-head NT [256,64]x[768,64]^T
    {
        EpiQK e{p_mk, p_Ak};
        gemm64_nt<<<dim3(DIM / 64, R_ROWS / 64, HEADS), TB>>>(p_q, INNER, HD, Wk, INNER, HD, HD, e);
    }

    // 10. qbk[bu,h] = q_h . bk_h
    qbk_kernel<<<(R_ROWS * HEADS * 32) / TB, TB>>>(p_q, bk, p_qbk);

    // 11. scores: per-batch NT [512,768] x [256,768]^T, epilogue (+qbk)/8
    {
        EpiScores e{p_qbk, p_w};
        gemm64_nt<<<dim3(V_ / 64, (HEADS * U_) / 64, BATCH), TB>>>(
            p_Ak, DIM, (long)HEADS * U_ * DIM, p_s, DIM, (long)V_ * DIM, DIM, e);
    }

    // 12. softmax over v (rows of 256)
    softmax256<<<BATCH * HEADS * U_, V_>>>(p_w);

    // 13. T = w @ s : per-batch NN [512,256] x [256,768]
    {
        EpiPlain e{p_T, DIM, (long)HEADS * U_ * DIM, nullptr, 0};
        gemm64_nn<<<dim3(DIM / 64, (HEADS * U_) / 64, BATCH), TB>>>(
            p_w, V_, (long)HEADS * U_ * V_, p_s, DIM, (long)V_ * DIM, V_, e);
    }

    // 14. Tm[h][bu][i] = T * (1+mv), remapped per-head
    tmv_kernel<<<(HEADS * R_ROWS * DIM) / TB, TB>>>(p_T, p_mv, p_Tm);

    // 15. msg_h = Tm_h @ Wv[:,h] + bv_h : per-head NN [256,768]x[768,64]
    {
        EpiPlain e{p_msg, INNER, HD, bv, HD};
        gemm64_nn<<<dim3(1, R_ROWS / 64, HEADS), TB>>>(
            p_Tm, DIM, (long)R_ROWS * DIM, Wv, INNER, HD, DIM, e);
    }

    // 16. msg *= (1+me)
    msgmod_kernel<<<(R_ROWS * INNER) / TB, TB>>>(p_msg, p_me);

    // 17. out = recv + (msg @ We + be)*gamma : [256,512]x[512,768]
    {
        EpiOut e{recv, be, gamma, out};
        gemm64_nn<<<dim3(DIM / 64, R_ROWS / 64, 1), TB>>>(p_msg, INNER, 0, We, DIM, 0, INNER, e);
    }
}